// round 8
// baseline (speedup 1.0000x reference)
#include <cuda_runtime.h>

#define N_USERS 50000
#define N_ENT   150000
#define NN      200000   // N_USERS + N_ENT
#define EE      2000000
#define BB      8192
#define CHUNK   1024
#define NBLK    ((NN + CHUNK - 1) / CHUNK)   // 196

// ---------------------------------------------------------------------------
// Device-global scratch
// ---------------------------------------------------------------------------
__device__ float g_A [(size_t)NN * 64];  // raw ego after layer 0
__device__ float g_Bu[(size_t)NN * 32];  // raw ego after layer 1
__device__ float g_N1[(size_t)NN * 64];  // l2norm after layer 0
__device__ float g_N2[(size_t)NN * 32];  // l2norm after layer 1
__device__ float g_N3[(size_t)NN * 16];  // l2norm after layer 2

// CSR structures
__device__ int    g_cnt[NN];
__device__ int    g_rowptr[NN + 1];
__device__ int    g_bsum[NBLK];
__device__ int    g_boff[NBLK];
__device__ float2 g_edges[EE];       // packed (col_as_float_bits, val)

__device__ __forceinline__ float leaky(float x) {
    return x >= 0.f ? x : 0.01f * x;
}

// packed f32x2 helpers
__device__ __forceinline__ unsigned long long pk2(float x, float y) {
    unsigned long long r;
    asm("mov.b64 %0, {%1, %2};" : "=l"(r) : "f"(x), "f"(y));
    return r;
}
__device__ __forceinline__ void upk2(unsigned long long v, float& x, float& y) {
    asm("mov.b64 {%0, %1}, %2;" : "=f"(x), "=f"(y) : "l"(v));
}
__device__ __forceinline__ unsigned long long f2fma(unsigned long long a,
                                                    unsigned long long b,
                                                    unsigned long long c) {
    unsigned long long d;
    asm("fma.rn.f32x2 %0, %1, %2, %3;" : "=l"(d) : "l"(a), "l"(b), "l"(c));
    return d;
}

// ---------------------------------------------------------------------------
// CSR build
// ---------------------------------------------------------------------------
__global__ void zero_cnt() {
    int i = blockIdx.x * blockDim.x + threadIdx.x;
    if (i < NN) g_cnt[i] = 0;
}

__global__ void hist(const int* __restrict__ rows) {
    int e = blockIdx.x * blockDim.x + threadIdx.x;
    if (e < EE) atomicAdd(&g_cnt[rows[e]], 1);
}

__global__ void scan1() {
    __shared__ int sh[256];
    int b = blockIdx.x, t = threadIdx.x;
    int base = b * CHUNK + t * 4;
    int v[4]; int s = 0;
    #pragma unroll
    for (int j = 0; j < 4; j++) {
        int idx = base + j;
        v[j] = (idx < NN) ? g_cnt[idx] : 0;
        s += v[j];
    }
    sh[t] = s;
    __syncthreads();
    for (int off = 1; off < 256; off <<= 1) {
        int x = (t >= off) ? sh[t - off] : 0;
        __syncthreads();
        sh[t] += x;
        __syncthreads();
    }
    int excl = sh[t] - s;
    #pragma unroll
    for (int j = 0; j < 4; j++) {
        int idx = base + j;
        if (idx < NN) g_rowptr[idx] = excl;
        excl += v[j];
    }
    if (t == 255) g_bsum[b] = sh[255];
}

__global__ void scan2() {
    __shared__ int sh[256];
    int t = threadIdx.x;
    int v = (t < NBLK) ? g_bsum[t] : 0;
    sh[t] = v;
    __syncthreads();
    for (int off = 1; off < 256; off <<= 1) {
        int x = (t >= off) ? sh[t - off] : 0;
        __syncthreads();
        sh[t] += x;
        __syncthreads();
    }
    if (t < NBLK) g_boff[t] = sh[t] - v;
}

__global__ void scan3() {
    int i = blockIdx.x * blockDim.x + threadIdx.x;
    if (i < NN) {
        int r = g_rowptr[i] + g_boff[i / CHUNK];
        g_rowptr[i] = r;
        g_cnt[i]    = r;
    }
    if (i == 0) g_rowptr[NN] = EE;
}

__global__ void permute(const int* __restrict__ rows, const int* __restrict__ cols,
                        const float* __restrict__ vals) {
    int e = blockIdx.x * blockDim.x + threadIdx.x;
    if (e < EE) {
        int r = rows[e];
        int p = atomicAdd(&g_cnt[r], 1);
        g_edges[p] = make_float2(__int_as_float(cols[e]), vals[e]);
    }
}

// ---------------------------------------------------------------------------
// Fused layer.  Per 64-node block:
//   Phase A (warp = 8 nodes): side = sum val*ego[col]  (CSR gather)
//       A-tile stored duplicated+interleaved: float4 = (h1,h1,h2,h2) per (row,k)
//       so Phase B's LDS.128 yields two ready-made fma.f32x2 operand pairs.
//   Phase B (16x16 GEMM): out = leaky(h1@Wg+bg) + leaky(h2@Wb+bb)
//       per k: 4x LDS.128 (A) + 2x LDS.128 (W) + 16 FFMA2, zero packing movs.
// ---------------------------------------------------------------------------
__device__ float* rawbuf(int id) { return id == 1 ? g_A : g_Bu; }
__device__ float* normbuf(int id) { return id == 3 ? g_N1 : (id == 4 ? g_N2 : g_N3); }

template <int DIN, int DOUT, bool WRITE_RAW>
__global__ void fused_layer(int ego_id,
                            const float* __restrict__ ue, const float* __restrict__ ee,
                            const float* __restrict__ Wg, const float* __restrict__ bg,
                            const float* __restrict__ Wb, const float* __restrict__ bb,
                            int raw_id, int norm_id) {
    extern __shared__ float sm[];
    float4* sA4 = (float4*)sm;                 // 64 * DIN float4 (dup/interleaved)
    float*  sWg = sm + (size_t)64 * DIN * 4;   // DIN*DOUT
    float*  sWb = sWg + DIN * DOUT;            // DIN*DOUT

    int tid  = threadIdx.x;
    int base = blockIdx.x * 64;

    const float* su;
    const float* se;
    if (ego_id == 0) { su = ue; se = ee; }
    else             { const float* p = rawbuf(ego_id); su = p; se = p + (size_t)N_USERS * DIN; }

    // stage weights
    for (int i = tid; i < DIN * DOUT; i += 256) { sWg[i] = Wg[i]; sWb[i] = Wb[i]; }

    // ---- Phase A: CSR gather -> duplicated/interleaved A tile ----
    int w    = tid >> 5;
    int lane = tid & 31;

    #pragma unroll 1
    for (int j = 0; j < 8; j++) {
        int n  = base + w * 8 + j;
        int s0 = g_rowptr[n];
        int s1 = g_rowptr[n + 1];
        int lr = w * 8 + j;

        if (DIN == 64) {
            float2 acc = make_float2(0.f, 0.f);
            for (int e0 = s0; e0 < s1; e0 += 32) {
                int m = min(32, s1 - e0);
                float2 ev = make_float2(0.f, 0.f);
                if (lane < m) ev = g_edges[e0 + lane];
                for (int jj = 0; jj < m; jj++) {
                    int   c = __shfl_sync(0xffffffffu, __float_as_int(ev.x), jj);
                    float v = __shfl_sync(0xffffffffu, ev.y, jj);
                    const float* src = (c < N_USERS) ? su + (size_t)c * 64
                                                     : se + (size_t)(c - N_USERS) * 64;
                    float2 g = ((const float2*)src)[lane];
                    acc.x += v * g.x;
                    acc.y += v * g.y;
                }
            }
            const float* eg = (n < N_USERS) ? su + (size_t)n * 64
                                            : se + (size_t)(n - N_USERS) * 64;
            float2 e = ((const float2*)eg)[lane];
            float h1x = e.x + acc.x, h2x = e.x * acc.x;
            float h1y = e.y + acc.y, h2y = e.y * acc.y;
            sA4[lr * DIN + 2 * lane]     = make_float4(h1x, h1x, h2x, h2x);
            sA4[lr * DIN + 2 * lane + 1] = make_float4(h1y, h1y, h2y, h2y);
        } else {  // DIN == 32
            float acc = 0.f;
            for (int e0 = s0; e0 < s1; e0 += 32) {
                int m = min(32, s1 - e0);
                float2 ev = make_float2(0.f, 0.f);
                if (lane < m) ev = g_edges[e0 + lane];
                for (int jj = 0; jj < m; jj++) {
                    int   c = __shfl_sync(0xffffffffu, __float_as_int(ev.x), jj);
                    float v = __shfl_sync(0xffffffffu, ev.y, jj);
                    const float* src = (c < N_USERS) ? su + (size_t)c * 32
                                                     : se + (size_t)(c - N_USERS) * 32;
                    acc += v * src[lane];
                }
            }
            const float* eg = (n < N_USERS) ? su + (size_t)n * 32
                                            : se + (size_t)(n - N_USERS) * 32;
            float e = eg[lane];
            float h1 = e + acc, h2 = e * acc;
            sA4[lr * DIN + lane] = make_float4(h1, h1, h2, h2);
        }
    }
    __syncthreads();

    // ---- Phase B: GEMM ----
    int ty = tid >> 4, tx = tid & 15;
    constexpr int CPT = DOUT / 16;
    int colb = tx * CPT;

    float o[4][CPT];
    float ss[4] = {0.f, 0.f, 0.f, 0.f};

    if (CPT >= 2) {
        constexpr int C2 = (CPT >= 2) ? CPT / 2 : 1;
        unsigned long long accg[4][C2], accb[4][C2];
        #pragma unroll
        for (int c2 = 0; c2 < C2; c2++) {
            unsigned long long vg = pk2(bg[colb + 2 * c2], bg[colb + 2 * c2 + 1]);
            unsigned long long vb = pk2(bb[colb + 2 * c2], bb[colb + 2 * c2 + 1]);
            #pragma unroll
            for (int i = 0; i < 4; i++) { accg[i][c2] = vg; accb[i][c2] = vb; }
        }
        #pragma unroll 4
        for (int k = 0; k < DIN; k++) {
            unsigned long long pa1[4], pa2[4];
            #pragma unroll
            for (int i = 0; i < 4; i++) {
                ulonglong2 a = *(const ulonglong2*)(sA4 + (ty * 4 + i) * DIN + k);
                pa1[i] = a.x;   // (h1, h1)
                pa2[i] = a.y;   // (h2, h2)
            }
            unsigned long long wgp[C2], wbp[C2];
            if (C2 == 2) {
                ulonglong2 wgv = *(const ulonglong2*)(sWg + k * DOUT + colb);
                ulonglong2 wbv = *(const ulonglong2*)(sWb + k * DOUT + colb);
                wgp[0] = wgv.x; wgp[C2 - 1] = wgv.y;
                wbp[0] = wbv.x; wbp[C2 - 1] = wbv.y;
            } else {
                wgp[0] = *(const unsigned long long*)(sWg + k * DOUT + colb);
                wbp[0] = *(const unsigned long long*)(sWb + k * DOUT + colb);
            }
            #pragma unroll
            for (int c2 = 0; c2 < C2; c2++) {
                #pragma unroll
                for (int i = 0; i < 4; i++) {
                    accg[i][c2] = f2fma(pa1[i], wgp[c2], accg[i][c2]);
                    accb[i][c2] = f2fma(pa2[i], wbp[c2], accb[i][c2]);
                }
            }
        }
        #pragma unroll
        for (int i = 0; i < 4; i++) {
            #pragma unroll
            for (int c2 = 0; c2 < C2; c2++) {
                float g0, g1, b0, b1;
                upk2(accg[i][c2], g0, g1);
                upk2(accb[i][c2], b0, b1);
                float x0 = leaky(g0) + leaky(b0);
                float x1 = leaky(g1) + leaky(b1);
                o[i][2 * c2]     = x0;
                o[i][2 * c2 + 1] = x1;
                ss[i] += x0 * x0 + x1 * x1;
            }
        }
    } else {
        float accg[4], accb[4];
        float big = bg[colb], bib = bb[colb];
        #pragma unroll
        for (int i = 0; i < 4; i++) { accg[i] = big; accb[i] = bib; }
        #pragma unroll 4
        for (int k = 0; k < DIN; k++) {
            float wgv = sWg[k * DOUT + colb];
            float wbv = sWb[k * DOUT + colb];
            #pragma unroll
            for (int i = 0; i < 4; i++) {
                float4 a = sA4[(ty * 4 + i) * DIN + k];
                accg[i] += a.x * wgv;
                accb[i] += a.z * wbv;
            }
        }
        #pragma unroll
        for (int i = 0; i < 4; i++) {
            float x = leaky(accg[i]) + leaky(accb[i]);
            o[i][0] = x;
            ss[i] += x * x;
        }
    }

    #pragma unroll
    for (int off = 8; off > 0; off >>= 1) {
        #pragma unroll
        for (int i = 0; i < 4; i++)
            ss[i] += __shfl_xor_sync(0xffffffffu, ss[i], off, 16);
    }

    float* oraw  = rawbuf(raw_id);
    float* onorm = normbuf(norm_id);
    #pragma unroll
    for (int i = 0; i < 4; i++) {
        float inv = 1.0f / fmaxf(sqrtf(ss[i]), 1e-12f);
        size_t rb = (size_t)(base + ty * 4 + i) * DOUT + colb;
        #pragma unroll
        for (int c = 0; c < CPT; c++) {
            if (WRITE_RAW) oraw[rb + c] = o[i][c];
            onorm[rb + c] = o[i][c] * inv;
        }
    }
}

// ---------------------------------------------------------------------------
// Final scoring: one warp per batch element.
// all_emb = [ego0(64) | N1(64) | N2(32) | N3(16)]  (176)
// ---------------------------------------------------------------------------
__global__ void final_score(const int* __restrict__ users,
                            const int* __restrict__ pos,
                            const int* __restrict__ neg,
                            const float* __restrict__ ue,
                            const float* __restrict__ ee,
                            float* __restrict__ out) {
    int t    = blockIdx.x * blockDim.x + threadIdx.x;
    int w    = t >> 5;
    int lane = t & 31;
    if (w >= BB) return;

    int u  = users[w];
    int pe = pos[w];
    int ne = neg[w];
    int p  = N_USERS + pe;
    int n  = N_USERS + ne;

    float sp = 0.f, sn = 0.f;

    #pragma unroll
    for (int j = 0; j < 2; j++) {
        int k = j * 32 + lane;
        float au = ue[(size_t)u  * 64 + k];
        float ap = ee[(size_t)pe * 64 + k];
        float an = ee[(size_t)ne * 64 + k];
        sp += au * ap; sn += au * an;
    }
    #pragma unroll
    for (int j = 0; j < 2; j++) {
        int k = j * 32 + lane;
        float au = g_N1[(size_t)u * 64 + k];
        float ap = g_N1[(size_t)p * 64 + k];
        float an = g_N1[(size_t)n * 64 + k];
        sp += au * ap; sn += au * an;
    }
    {
        float au = g_N2[(size_t)u * 32 + lane];
        float ap = g_N2[(size_t)p * 32 + lane];
        float an = g_N2[(size_t)n * 32 + lane];
        sp += au * ap; sn += au * an;
    }
    if (lane < 16) {
        float au = g_N3[(size_t)u * 16 + lane];
        float ap = g_N3[(size_t)p * 16 + lane];
        float an = g_N3[(size_t)n * 16 + lane];
        sp += au * ap; sn += au * an;
    }

    #pragma unroll
    for (int off = 16; off > 0; off >>= 1) {
        sp += __shfl_xor_sync(0xffffffffu, sp, off);
        sn += __shfl_xor_sync(0xffffffffu, sn, off);
    }
    if (lane == 0) {
        out[(size_t)w * 2 + 0] = sp;
        out[(size_t)w * 2 + 1] = sn;
    }
}

// ---------------------------------------------------------------------------
// Launch
// ---------------------------------------------------------------------------
extern "C" void kernel_launch(void* const* d_in, const int* in_sizes, int n_in,
                              void* d_out, int out_size) {
    const int*   users = (const int*)  d_in[0];
    const int*   pos   = (const int*)  d_in[1];
    const int*   neg   = (const int*)  d_in[2];
    const int*   rows  = (const int*)  d_in[3];
    const int*   cols  = (const int*)  d_in[4];
    const float* vals  = (const float*)d_in[5];
    const float* ue    = (const float*)d_in[6];
    const float* ee    = (const float*)d_in[7];
    const float* Wg0 = (const float*)d_in[8],  *bg0 = (const float*)d_in[9];
    const float* Wb0 = (const float*)d_in[10], *bb0 = (const float*)d_in[11];
    const float* Wg1 = (const float*)d_in[12], *bg1 = (const float*)d_in[13];
    const float* Wb1 = (const float*)d_in[14], *bb1 = (const float*)d_in[15];
    const float* Wg2 = (const float*)d_in[16], *bg2 = (const float*)d_in[17];
    const float* Wb2 = (const float*)d_in[18], *bb2 = (const float*)d_in[19];
    float* out = (float*)d_out;

    // dynamic smem: A dup tile (64*DIN*16B) + 2 weight mats
    const int smem0 = 64 * 64 * 16 + 2 * 64 * 64 * 4;  // 98304
    const int smem1 = 64 * 64 * 16 + 2 * 64 * 32 * 4;  // 81920
    const int smem2 = 64 * 32 * 16 + 2 * 32 * 16 * 4;  // 36864
    cudaFuncSetAttribute((const void*)fused_layer<64, 64, true>,
                         cudaFuncAttributeMaxDynamicSharedMemorySize, smem0);
    cudaFuncSetAttribute((const void*)fused_layer<64, 32, true>,
                         cudaFuncAttributeMaxDynamicSharedMemorySize, smem1);

    // ---- CSR build ----
    zero_cnt<<<(NN + 255) / 256, 256>>>();
    hist<<<(EE + 255) / 256, 256>>>(rows);
    scan1<<<NBLK, 256>>>();
    scan2<<<1, 256>>>();
    scan3<<<(NN + 255) / 256, 256>>>();
    permute<<<(EE + 255) / 256, 256>>>(rows, cols, vals);

    const int gemm_blocks = NN / 64;   // 3125 exact

    // ---- Layer 0: 64 -> 64 ----
    fused_layer<64, 64, true><<<gemm_blocks, 256, smem0>>>(
        0, ue, ee, Wg0, bg0, Wb0, bb0, 1, 3);

    // ---- Layer 1: 64 -> 32 ----
    fused_layer<64, 32, true><<<gemm_blocks, 256, smem1>>>(
        1, ue, ee, Wg1, bg1, Wb1, bb1, 2, 4);

    // ---- Layer 2: 32 -> 16 ----
    fused_layer<32, 16, false><<<gemm_blocks, 256, smem2>>>(
        2, ue, ee, Wg2, bg2, Wb2, bb2, 1, 5);

    // ---- Final scoring ----
    final_score<<<(BB * 32 + 255) / 256, 256>>>(users, pos, neg, ue, ee, out);
}

// round 9
// speedup vs baseline: 1.7457x; 1.7457x over previous
#include <cuda_runtime.h>

#define N_USERS 50000
#define N_ENT   150000
#define NN      200000   // N_USERS + N_ENT
#define EE      2000000
#define BB      8192
#define CHUNK   1024
#define NBLK    ((NN + CHUNK - 1) / CHUNK)   // 196

// ---------------------------------------------------------------------------
// Device-global scratch
// ---------------------------------------------------------------------------
__device__ float g_A [(size_t)NN * 64];  // raw ego after layer 0
__device__ float g_Bu[(size_t)NN * 32];  // raw ego after layer 1
__device__ float g_N1[(size_t)NN * 64];  // l2norm after layer 0
__device__ float g_N2[(size_t)NN * 32];  // l2norm after layer 1
__device__ float g_N3[(size_t)NN * 16];  // l2norm after layer 2

// CSR structures
__device__ int    g_cnt[NN];
__device__ int    g_rowptr[NN + 1];
__device__ int    g_bsum[NBLK];
__device__ int    g_boff[NBLK];
__device__ float2 g_edges[EE];       // packed (col_as_float_bits, val)

__device__ __forceinline__ float leaky(float x) {
    return x >= 0.f ? x : 0.01f * x;
}

// packed f32x2 helpers
__device__ __forceinline__ unsigned long long pk2(float x, float y) {
    unsigned long long r;
    asm("mov.b64 %0, {%1, %2};" : "=l"(r) : "f"(x), "f"(y));
    return r;
}
__device__ __forceinline__ void upk2(unsigned long long v, float& x, float& y) {
    asm("mov.b64 {%0, %1}, %2;" : "=f"(x), "=f"(y) : "l"(v));
}
__device__ __forceinline__ unsigned long long f2fma(unsigned long long a,
                                                    unsigned long long b,
                                                    unsigned long long c) {
    unsigned long long d;
    asm("fma.rn.f32x2 %0, %1, %2, %3;" : "=l"(d) : "l"(a), "l"(b), "l"(c));
    return d;
}

// ---------------------------------------------------------------------------
// CSR build
// ---------------------------------------------------------------------------
__global__ void zero_cnt() {
    int i = blockIdx.x * blockDim.x + threadIdx.x;
    if (i < NN) g_cnt[i] = 0;
}

__global__ void hist(const int* __restrict__ rows) {
    int e = blockIdx.x * blockDim.x + threadIdx.x;
    if (e < EE) atomicAdd(&g_cnt[rows[e]], 1);
}

__global__ void scan1() {
    __shared__ int sh[256];
    int b = blockIdx.x, t = threadIdx.x;
    int base = b * CHUNK + t * 4;
    int v[4]; int s = 0;
    #pragma unroll
    for (int j = 0; j < 4; j++) {
        int idx = base + j;
        v[j] = (idx < NN) ? g_cnt[idx] : 0;
        s += v[j];
    }
    sh[t] = s;
    __syncthreads();
    for (int off = 1; off < 256; off <<= 1) {
        int x = (t >= off) ? sh[t - off] : 0;
        __syncthreads();
        sh[t] += x;
        __syncthreads();
    }
    int excl = sh[t] - s;
    #pragma unroll
    for (int j = 0; j < 4; j++) {
        int idx = base + j;
        if (idx < NN) g_rowptr[idx] = excl;
        excl += v[j];
    }
    if (t == 255) g_bsum[b] = sh[255];
}

__global__ void scan2() {
    __shared__ int sh[256];
    int t = threadIdx.x;
    int v = (t < NBLK) ? g_bsum[t] : 0;
    sh[t] = v;
    __syncthreads();
    for (int off = 1; off < 256; off <<= 1) {
        int x = (t >= off) ? sh[t - off] : 0;
        __syncthreads();
        sh[t] += x;
        __syncthreads();
    }
    if (t < NBLK) g_boff[t] = sh[t] - v;
}

__global__ void scan3() {
    int i = blockIdx.x * blockDim.x + threadIdx.x;
    if (i < NN) {
        int r = g_rowptr[i] + g_boff[i / CHUNK];
        g_rowptr[i] = r;
        g_cnt[i]    = r;
    }
    if (i == 0) g_rowptr[NN] = EE;
}

__global__ void permute(const int* __restrict__ rows, const int* __restrict__ cols,
                        const float* __restrict__ vals) {
    int e = blockIdx.x * blockDim.x + threadIdx.x;
    if (e < EE) {
        int r = rows[e];
        int p = atomicAdd(&g_cnt[r], 1);
        g_edges[p] = make_float2(__int_as_float(cols[e]), vals[e]);
    }
}

// ---------------------------------------------------------------------------
// Fused layer.  Per 64-node block:
//   Phase A: warp split into two 16-lane groups, each group one node at a
//            time (2 nodes concurrently per warp -> 2x MLP on the L2 gather,
//            16B/lane float4 loads).  side accumulated in registers.
//            sA1 = ego+side, sA2 = ego*side in padded smem (LDA = DIN+1).
//   Phase B: 16x16 register-tiled GEMM with fma.rn.f32x2 (R7 layout).
// ---------------------------------------------------------------------------
__device__ float* rawbuf(int id) { return id == 1 ? g_A : g_Bu; }
__device__ float* normbuf(int id) { return id == 3 ? g_N1 : (id == 4 ? g_N2 : g_N3); }

template <int DIN, int DOUT, bool WRITE_RAW>
__global__ void fused_layer(int ego_id,
                            const float* __restrict__ ue, const float* __restrict__ ee,
                            const float* __restrict__ Wg, const float* __restrict__ bg,
                            const float* __restrict__ Wb, const float* __restrict__ bb,
                            int raw_id, int norm_id) {
    extern __shared__ float sm[];
    constexpr int LDA = DIN + 1;
    float* sA1 = sm;
    float* sA2 = sA1 + 64 * LDA;
    float* sWg = sA2 + 64 * LDA;
    float* sWb = sWg + DIN * DOUT;

    int tid  = threadIdx.x;
    int base = blockIdx.x * 64;

    const float* su;
    const float* se;
    if (ego_id == 0) { su = ue; se = ee; }
    else             { const float* p = rawbuf(ego_id); su = p; se = p + (size_t)N_USERS * DIN; }

    // stage weights
    for (int i = tid; i < DIN * DOUT; i += 256) { sWg[i] = Wg[i]; sWb[i] = Wb[i]; }

    // ---- Phase A: CSR gather, 2 nodes per warp concurrently ----
    int w    = tid >> 5;
    int lane = tid & 31;
    int grp  = lane >> 4;      // 0 or 1
    int sl   = lane & 15;

    #pragma unroll 1
    for (int j = 0; j < 4; j++) {
        int lr = w * 8 + j * 2 + grp;
        int n  = base + lr;
        int s0 = g_rowptr[n];
        int s1 = g_rowptr[n + 1];
        int len  = s1 - s0;
        int olen = __shfl_xor_sync(0xffffffffu, len, 16);
        int lmax = max(len, olen);

        if (DIN == 64) {
            float4 acc = make_float4(0.f, 0.f, 0.f, 0.f);
            for (int t0 = 0; t0 < lmax; t0 += 16) {
                int m  = min(16, len - t0);            // may be <= 0
                int mm = min(16, lmax - t0);
                float2 ev = make_float2(__int_as_float(0), 0.f);
                if (sl < m) ev = g_edges[s0 + t0 + sl];
                for (int jj = 0; jj < mm; jj++) {
                    int   c = __shfl_sync(0xffffffffu, __float_as_int(ev.x), jj, 16);
                    float v = __shfl_sync(0xffffffffu, ev.y, jj, 16);
                    const float* src = (c < N_USERS) ? su + (size_t)c * 64
                                                     : se + (size_t)(c - N_USERS) * 64;
                    float4 g = ((const float4*)src)[sl];
                    acc.x += v * g.x;
                    acc.y += v * g.y;
                    acc.z += v * g.z;
                    acc.w += v * g.w;
                }
            }
            const float* eg = (n < N_USERS) ? su + (size_t)n * 64
                                            : se + (size_t)(n - N_USERS) * 64;
            float4 e = ((const float4*)eg)[sl];
            int kb = sl * 4;
            sA1[lr * LDA + kb + 0] = e.x + acc.x;
            sA1[lr * LDA + kb + 1] = e.y + acc.y;
            sA1[lr * LDA + kb + 2] = e.z + acc.z;
            sA1[lr * LDA + kb + 3] = e.w + acc.w;
            sA2[lr * LDA + kb + 0] = e.x * acc.x;
            sA2[lr * LDA + kb + 1] = e.y * acc.y;
            sA2[lr * LDA + kb + 2] = e.z * acc.z;
            sA2[lr * LDA + kb + 3] = e.w * acc.w;
        } else {  // DIN == 32
            float2 acc = make_float2(0.f, 0.f);
            for (int t0 = 0; t0 < lmax; t0 += 16) {
                int m  = min(16, len - t0);
                int mm = min(16, lmax - t0);
                float2 ev = make_float2(__int_as_float(0), 0.f);
                if (sl < m) ev = g_edges[s0 + t0 + sl];
                for (int jj = 0; jj < mm; jj++) {
                    int   c = __shfl_sync(0xffffffffu, __float_as_int(ev.x), jj, 16);
                    float v = __shfl_sync(0xffffffffu, ev.y, jj, 16);
                    const float* src = (c < N_USERS) ? su + (size_t)c * 32
                                                     : se + (size_t)(c - N_USERS) * 32;
                    float2 g = ((const float2*)src)[sl];
                    acc.x += v * g.x;
                    acc.y += v * g.y;
                }
            }
            const float* eg = (n < N_USERS) ? su + (size_t)n * 32
                                            : se + (size_t)(n - N_USERS) * 32;
            float2 e = ((const float2*)eg)[sl];
            int kb = sl * 2;
            sA1[lr * LDA + kb + 0] = e.x + acc.x;
            sA1[lr * LDA + kb + 1] = e.y + acc.y;
            sA2[lr * LDA + kb + 0] = e.x * acc.x;
            sA2[lr * LDA + kb + 1] = e.y * acc.y;
        }
    }
    __syncthreads();

    // ---- Phase B: GEMM (R7 layout) ----
    int ty = tid >> 4, tx = tid & 15;
    constexpr int CPT = DOUT / 16;
    int colb = tx * CPT;

    float o[4][CPT];
    float ss[4] = {0.f, 0.f, 0.f, 0.f};

    if (CPT >= 2) {
        constexpr int C2 = (CPT >= 2) ? CPT / 2 : 1;
        unsigned long long accg[4][C2], accb[4][C2];
        #pragma unroll
        for (int c2 = 0; c2 < C2; c2++) {
            unsigned long long vg = pk2(bg[colb + 2 * c2], bg[colb + 2 * c2 + 1]);
            unsigned long long vb = pk2(bb[colb + 2 * c2], bb[colb + 2 * c2 + 1]);
            #pragma unroll
            for (int i = 0; i < 4; i++) { accg[i][c2] = vg; accb[i][c2] = vb; }
        }
        #pragma unroll 4
        for (int k = 0; k < DIN; k++) {
            unsigned long long pa1[4], pa2[4];
            #pragma unroll
            for (int i = 0; i < 4; i++) {
                float a1 = sA1[(ty * 4 + i) * LDA + k];
                float a2 = sA2[(ty * 4 + i) * LDA + k];
                pa1[i] = pk2(a1, a1);
                pa2[i] = pk2(a2, a2);
            }
            #pragma unroll
            for (int c2 = 0; c2 < C2; c2++) {
                unsigned long long wg = *(const unsigned long long*)(sWg + k * DOUT + colb + 2 * c2);
                unsigned long long wb = *(const unsigned long long*)(sWb + k * DOUT + colb + 2 * c2);
                #pragma unroll
                for (int i = 0; i < 4; i++) {
                    accg[i][c2] = f2fma(pa1[i], wg, accg[i][c2]);
                    accb[i][c2] = f2fma(pa2[i], wb, accb[i][c2]);
                }
            }
        }
        #pragma unroll
        for (int i = 0; i < 4; i++) {
            #pragma unroll
            for (int c2 = 0; c2 < C2; c2++) {
                float g0, g1, b0, b1;
                upk2(accg[i][c2], g0, g1);
                upk2(accb[i][c2], b0, b1);
                float x0 = leaky(g0) + leaky(b0);
                float x1 = leaky(g1) + leaky(b1);
                o[i][2 * c2]     = x0;
                o[i][2 * c2 + 1] = x1;
                ss[i] += x0 * x0 + x1 * x1;
            }
        }
    } else {
        float accg[4], accb[4];
        float big = bg[colb], bib = bb[colb];
        #pragma unroll
        for (int i = 0; i < 4; i++) { accg[i] = big; accb[i] = bib; }
        #pragma unroll 4
        for (int k = 0; k < DIN; k++) {
            float wgv = sWg[k * DOUT + colb];
            float wbv = sWb[k * DOUT + colb];
            #pragma unroll
            for (int i = 0; i < 4; i++) {
                accg[i] += sA1[(ty * 4 + i) * LDA + k] * wgv;
                accb[i] += sA2[(ty * 4 + i) * LDA + k] * wbv;
            }
        }
        #pragma unroll
        for (int i = 0; i < 4; i++) {
            float x = leaky(accg[i]) + leaky(accb[i]);
            o[i][0] = x;
            ss[i] += x * x;
        }
    }

    #pragma unroll
    for (int off = 8; off > 0; off >>= 1) {
        #pragma unroll
        for (int i = 0; i < 4; i++)
            ss[i] += __shfl_xor_sync(0xffffffffu, ss[i], off, 16);
    }

    float* oraw  = rawbuf(raw_id);
    float* onorm = normbuf(norm_id);
    #pragma unroll
    for (int i = 0; i < 4; i++) {
        float inv = 1.0f / fmaxf(sqrtf(ss[i]), 1e-12f);
        size_t rb = (size_t)(base + ty * 4 + i) * DOUT + colb;
        #pragma unroll
        for (int c = 0; c < CPT; c++) {
            if (WRITE_RAW) oraw[rb + c] = o[i][c];
            onorm[rb + c] = o[i][c] * inv;
        }
    }
}

// ---------------------------------------------------------------------------
// Final scoring: one warp per batch element.
// ---------------------------------------------------------------------------
__global__ void final_score(const int* __restrict__ users,
                            const int* __restrict__ pos,
                            const int* __restrict__ neg,
                            const float* __restrict__ ue,
                            const float* __restrict__ ee,
                            float* __restrict__ out) {
    int t    = blockIdx.x * blockDim.x + threadIdx.x;
    int w    = t >> 5;
    int lane = t & 31;
    if (w >= BB) return;

    int u  = users[w];
    int pe = pos[w];
    int ne = neg[w];
    int p  = N_USERS + pe;
    int n  = N_USERS + ne;

    float sp = 0.f, sn = 0.f;

    #pragma unroll
    for (int j = 0; j < 2; j++) {
        int k = j * 32 + lane;
        float au = ue[(size_t)u  * 64 + k];
        float ap = ee[(size_t)pe * 64 + k];
        float an = ee[(size_t)ne * 64 + k];
        sp += au * ap; sn += au * an;
    }
    #pragma unroll
    for (int j = 0; j < 2; j++) {
        int k = j * 32 + lane;
        float au = g_N1[(size_t)u * 64 + k];
        float ap = g_N1[(size_t)p * 64 + k];
        float an = g_N1[(size_t)n * 64 + k];
        sp += au * ap; sn += au * an;
    }
    {
        float au = g_N2[(size_t)u * 32 + lane];
        float ap = g_N2[(size_t)p * 32 + lane];
        float an = g_N2[(size_t)n * 32 + lane];
        sp += au * ap; sn += au * an;
    }
    if (lane < 16) {
        float au = g_N3[(size_t)u * 16 + lane];
        float ap = g_N3[(size_t)p * 16 + lane];
        float an = g_N3[(size_t)n * 16 + lane];
        sp += au * ap; sn += au * an;
    }

    #pragma unroll
    for (int off = 16; off > 0; off >>= 1) {
        sp += __shfl_xor_sync(0xffffffffu, sp, off);
        sn += __shfl_xor_sync(0xffffffffu, sn, off);
    }
    if (lane == 0) {
        out[(size_t)w * 2 + 0] = sp;
        out[(size_t)w * 2 + 1] = sn;
    }
}

// ---------------------------------------------------------------------------
// Launch
// ---------------------------------------------------------------------------
extern "C" void kernel_launch(void* const* d_in, const int* in_sizes, int n_in,
                              void* d_out, int out_size) {
    const int*   users = (const int*)  d_in[0];
    const int*   pos   = (const int*)  d_in[1];
    const int*   neg   = (const int*)  d_in[2];
    const int*   rows  = (const int*)  d_in[3];
    const int*   cols  = (const int*)  d_in[4];
    const float* vals  = (const float*)d_in[5];
    const float* ue    = (const float*)d_in[6];
    const float* ee    = (const float*)d_in[7];
    const float* Wg0 = (const float*)d_in[8],  *bg0 = (const float*)d_in[9];
    const float* Wb0 = (const float*)d_in[10], *bb0 = (const float*)d_in[11];
    const float* Wg1 = (const float*)d_in[12], *bg1 = (const float*)d_in[13];
    const float* Wb1 = (const float*)d_in[14], *bb1 = (const float*)d_in[15];
    const float* Wg2 = (const float*)d_in[16], *bg2 = (const float*)d_in[17];
    const float* Wb2 = (const float*)d_in[18], *bb2 = (const float*)d_in[19];
    float* out = (float*)d_out;

    const int smem0 = (2 * 64 * 65 + 2 * 64 * 64) * 4;  // 66048
    const int smem1 = (2 * 64 * 65 + 2 * 64 * 32) * 4;  // 49664
    const int smem2 = (2 * 64 * 33 + 2 * 32 * 16) * 4;  // 20992
    cudaFuncSetAttribute((const void*)fused_layer<64, 64, true>,
                         cudaFuncAttributeMaxDynamicSharedMemorySize, smem0);
    cudaFuncSetAttribute((const void*)fused_layer<64, 32, true>,
                         cudaFuncAttributeMaxDynamicSharedMemorySize, smem1);

    // ---- CSR build ----
    zero_cnt<<<(NN + 255) / 256, 256>>>();
    hist<<<(EE + 255) / 256, 256>>>(rows);
    scan1<<<NBLK, 256>>>();
    scan2<<<1, 256>>>();
    scan3<<<(NN + 255) / 256, 256>>>();
    permute<<<(EE + 255) / 256, 256>>>(rows, cols, vals);

    const int gemm_blocks = NN / 64;   // 3125 exact

    // ---- Layer 0: 64 -> 64 ----
    fused_layer<64, 64, true><<<gemm_blocks, 256, smem0>>>(
        0, ue, ee, Wg0, bg0, Wb0, bb0, 1, 3);

    // ---- Layer 1: 64 -> 32 ----
    fused_layer<64, 32, true><<<gemm_blocks, 256, smem1>>>(
        1, ue, ee, Wg1, bg1, Wb1, bb1, 2, 4);

    // ---- Layer 2: 32 -> 16 ----
    fused_layer<32, 16, false><<<gemm_blocks, 256, smem2>>>(
        2, ue, ee, Wg2, bg2, Wb2, bb2, 1, 5);

    // ---- Final scoring ----
    final_score<<<(BB * 32 + 255) / 256, 256>>>(users, pos, neg, ue, ee, out);
}

// round 11
// speedup vs baseline: 1.8965x; 1.0864x over previous
#include <cuda_runtime.h>

#define N_USERS 50000
#define N_ENT   150000
#define NN      200000   // N_USERS + N_ENT
#define EE      2000000
#define BB      8192
#define CHUNK   1024
#define NBLK    ((NN + CHUNK - 1) / CHUNK)   // 196

// ---------------------------------------------------------------------------
// Device-global scratch
// ---------------------------------------------------------------------------
__device__ float g_A [(size_t)NN * 64];  // raw ego after layer 0
__device__ float g_Bu[(size_t)NN * 32];  // raw ego after layer 1
__device__ float g_N1[(size_t)NN * 64];  // l2norm after layer 0
__device__ float g_N2[(size_t)NN * 32];  // l2norm after layer 1
__device__ float g_N3[(size_t)NN * 16];  // l2norm after layer 2

// CSR structures
__device__ int    g_cnt[NN];
__device__ int    g_rowptr[NN + 1];
__device__ int    g_bsum[NBLK];
__device__ int    g_boff[NBLK];
__device__ float2 g_edges[EE];       // packed (col_as_float_bits, val)

__device__ __forceinline__ float leaky(float x) {
    return x >= 0.f ? x : 0.01f * x;
}

// packed f32x2 helpers
__device__ __forceinline__ unsigned long long pk2(float x, float y) {
    unsigned long long r;
    asm("mov.b64 %0, {%1, %2};" : "=l"(r) : "f"(x), "f"(y));
    return r;
}
__device__ __forceinline__ void upk2(unsigned long long v, float& x, float& y) {
    asm("mov.b64 {%0, %1}, %2;" : "=f"(x), "=f"(y) : "l"(v));
}
__device__ __forceinline__ unsigned long long f2fma(unsigned long long a,
                                                    unsigned long long b,
                                                    unsigned long long c) {
    unsigned long long d;
    asm("fma.rn.f32x2 %0, %1, %2, %3;" : "=l"(d) : "l"(a), "l"(b), "l"(c));
    return d;
}

// ---------------------------------------------------------------------------
// CSR build
// ---------------------------------------------------------------------------
__global__ void zero_cnt() {
    int i = blockIdx.x * blockDim.x + threadIdx.x;
    if (i < NN) g_cnt[i] = 0;
}

__global__ void hist(const int* __restrict__ rows) {
    int e = blockIdx.x * blockDim.x + threadIdx.x;
    if (e < EE) atomicAdd(&g_cnt[rows[e]], 1);
}

__global__ void scan1() {
    __shared__ int sh[256];
    int b = blockIdx.x, t = threadIdx.x;
    int base = b * CHUNK + t * 4;
    int v[4]; int s = 0;
    #pragma unroll
    for (int j = 0; j < 4; j++) {
        int idx = base + j;
        v[j] = (idx < NN) ? g_cnt[idx] : 0;
        s += v[j];
    }
    sh[t] = s;
    __syncthreads();
    for (int off = 1; off < 256; off <<= 1) {
        int x = (t >= off) ? sh[t - off] : 0;
        __syncthreads();
        sh[t] += x;
        __syncthreads();
    }
    int excl = sh[t] - s;
    #pragma unroll
    for (int j = 0; j < 4; j++) {
        int idx = base + j;
        if (idx < NN) g_rowptr[idx] = excl;
        excl += v[j];
    }
    if (t == 255) g_bsum[b] = sh[255];
}

__global__ void scan2() {
    __shared__ int sh[256];
    int t = threadIdx.x;
    int v = (t < NBLK) ? g_bsum[t] : 0;
    sh[t] = v;
    __syncthreads();
    for (int off = 1; off < 256; off <<= 1) {
        int x = (t >= off) ? sh[t - off] : 0;
        __syncthreads();
        sh[t] += x;
        __syncthreads();
    }
    if (t < NBLK) g_boff[t] = sh[t] - v;
}

__global__ void scan3() {
    int i = blockIdx.x * blockDim.x + threadIdx.x;
    if (i < NN) {
        int r = g_rowptr[i] + g_boff[i / CHUNK];
        g_rowptr[i] = r;
        g_cnt[i]    = r;
    }
    if (i == 0) g_rowptr[NN] = EE;
}

__global__ void permute(const int* __restrict__ rows, const int* __restrict__ cols,
                        const float* __restrict__ vals) {
    int e = blockIdx.x * blockDim.x + threadIdx.x;
    if (e < EE) {
        int r = rows[e];
        int p = atomicAdd(&g_cnt[r], 1);
        g_edges[p] = make_float2(__int_as_float(cols[e]), vals[e]);
    }
}

// ---------------------------------------------------------------------------
// Fused layer.  Per 64-node block:
//   Phase A: warp split into two 16-lane groups (2 nodes concurrently).
//            Inner edge loop batched by 4: issue 4 independent row loads,
//            then 4 FMAs -> MLP ~4 per group, ~8 per warp.
//            Out-of-range batch slots read (c=0, v=0) defaults (safe, wasted).
//   Phase B: 16x16 register-tiled GEMM with fma.rn.f32x2 (R7 layout).
// ---------------------------------------------------------------------------
__device__ float* rawbuf(int id) { return id == 1 ? g_A : g_Bu; }
__device__ float* normbuf(int id) { return id == 3 ? g_N1 : (id == 4 ? g_N2 : g_N3); }

template <int DIN, int DOUT, bool WRITE_RAW>
__global__ void fused_layer(int ego_id,
                            const float* __restrict__ ue, const float* __restrict__ ee,
                            const float* __restrict__ Wg, const float* __restrict__ bg,
                            const float* __restrict__ Wb, const float* __restrict__ bb,
                            int raw_id, int norm_id) {
    extern __shared__ float sm[];
    constexpr int LDA = DIN + 1;
    float* sA1 = sm;
    float* sA2 = sA1 + 64 * LDA;
    float* sWg = sA2 + 64 * LDA;
    float* sWb = sWg + DIN * DOUT;

    int tid  = threadIdx.x;
    int base = blockIdx.x * 64;

    const float* su;
    const float* se;
    if (ego_id == 0) { su = ue; se = ee; }
    else             { const float* p = rawbuf(ego_id); su = p; se = p + (size_t)N_USERS * DIN; }

    // stage weights
    for (int i = tid; i < DIN * DOUT; i += 256) { sWg[i] = Wg[i]; sWb[i] = Wb[i]; }

    // ---- Phase A: CSR gather, 2 nodes per warp, 4-edge load batches ----
    int w    = tid >> 5;
    int lane = tid & 31;
    int grp  = lane >> 4;      // 0 or 1
    int sl   = lane & 15;

    #pragma unroll 1
    for (int j = 0; j < 4; j++) {
        int lr = w * 8 + j * 2 + grp;
        int n  = base + lr;
        int s0 = g_rowptr[n];
        int s1 = g_rowptr[n + 1];
        int len  = s1 - s0;
        int olen = __shfl_xor_sync(0xffffffffu, len, 16);
        int lmax = max(len, olen);

        if (DIN == 64) {
            float4 acc = make_float4(0.f, 0.f, 0.f, 0.f);
            for (int t0 = 0; t0 < lmax; t0 += 16) {
                int m  = min(16, len - t0);            // valid edges this group
                int mm = min(16, lmax - t0);           // max across both groups
                float2 ev = make_float2(__int_as_float(0), 0.f);
                if (sl < m) ev = g_edges[s0 + t0 + sl];
                #pragma unroll 1
                for (int jj = 0; jj < mm; jj += 4) {
                    int   c0 = __shfl_sync(0xffffffffu, __float_as_int(ev.x), jj + 0, 16);
                    float v0 = __shfl_sync(0xffffffffu, ev.y, jj + 0, 16);
                    int   c1 = __shfl_sync(0xffffffffu, __float_as_int(ev.x), jj + 1, 16);
                    float v1 = __shfl_sync(0xffffffffu, ev.y, jj + 1, 16);
                    int   c2 = __shfl_sync(0xffffffffu, __float_as_int(ev.x), jj + 2, 16);
                    float v2 = __shfl_sync(0xffffffffu, ev.y, jj + 2, 16);
                    int   c3 = __shfl_sync(0xffffffffu, __float_as_int(ev.x), jj + 3, 16);
                    float v3 = __shfl_sync(0xffffffffu, ev.y, jj + 3, 16);
                    const float4* p0 = (const float4*)((c0 < N_USERS) ? su + (size_t)c0 * 64
                                                                      : se + (size_t)(c0 - N_USERS) * 64);
                    const float4* p1 = (const float4*)((c1 < N_USERS) ? su + (size_t)c1 * 64
                                                                      : se + (size_t)(c1 - N_USERS) * 64);
                    const float4* p2 = (const float4*)((c2 < N_USERS) ? su + (size_t)c2 * 64
                                                                      : se + (size_t)(c2 - N_USERS) * 64);
                    const float4* p3 = (const float4*)((c3 < N_USERS) ? su + (size_t)c3 * 64
                                                                      : se + (size_t)(c3 - N_USERS) * 64);
                    float4 g0 = p0[sl];
                    float4 g1 = p1[sl];
                    float4 g2 = p2[sl];
                    float4 g3 = p3[sl];
                    acc.x += v0 * g0.x; acc.y += v0 * g0.y; acc.z += v0 * g0.z; acc.w += v0 * g0.w;
                    acc.x += v1 * g1.x; acc.y += v1 * g1.y; acc.z += v1 * g1.z; acc.w += v1 * g1.w;
                    acc.x += v2 * g2.x; acc.y += v2 * g2.y; acc.z += v2 * g2.z; acc.w += v2 * g2.w;
                    acc.x += v3 * g3.x; acc.y += v3 * g3.y; acc.z += v3 * g3.z; acc.w += v3 * g3.w;
                }
            }
            const float* eg = (n < N_USERS) ? su + (size_t)n * 64
                                            : se + (size_t)(n - N_USERS) * 64;
            float4 e = ((const float4*)eg)[sl];
            int kb = sl * 4;
            sA1[lr * LDA + kb + 0] = e.x + acc.x;
            sA1[lr * LDA + kb + 1] = e.y + acc.y;
            sA1[lr * LDA + kb + 2] = e.z + acc.z;
            sA1[lr * LDA + kb + 3] = e.w + acc.w;
            sA2[lr * LDA + kb + 0] = e.x * acc.x;
            sA2[lr * LDA + kb + 1] = e.y * acc.y;
            sA2[lr * LDA + kb + 2] = e.z * acc.z;
            sA2[lr * LDA + kb + 3] = e.w * acc.w;
        } else {  // DIN == 32
            float2 acc = make_float2(0.f, 0.f);
            for (int t0 = 0; t0 < lmax; t0 += 16) {
                int m  = min(16, len - t0);
                int mm = min(16, lmax - t0);
                float2 ev = make_float2(__int_as_float(0), 0.f);
                if (sl < m) ev = g_edges[s0 + t0 + sl];
                #pragma unroll 1
                for (int jj = 0; jj < mm; jj += 4) {
                    int   c0 = __shfl_sync(0xffffffffu, __float_as_int(ev.x), jj + 0, 16);
                    float v0 = __shfl_sync(0xffffffffu, ev.y, jj + 0, 16);
                    int   c1 = __shfl_sync(0xffffffffu, __float_as_int(ev.x), jj + 1, 16);
                    float v1 = __shfl_sync(0xffffffffu, ev.y, jj + 1, 16);
                    int   c2 = __shfl_sync(0xffffffffu, __float_as_int(ev.x), jj + 2, 16);
                    float v2 = __shfl_sync(0xffffffffu, ev.y, jj + 2, 16);
                    int   c3 = __shfl_sync(0xffffffffu, __float_as_int(ev.x), jj + 3, 16);
                    float v3 = __shfl_sync(0xffffffffu, ev.y, jj + 3, 16);
                    const float2* p0 = (const float2*)((c0 < N_USERS) ? su + (size_t)c0 * 32
                                                                      : se + (size_t)(c0 - N_USERS) * 32);
                    const float2* p1 = (const float2*)((c1 < N_USERS) ? su + (size_t)c1 * 32
                                                                      : se + (size_t)(c1 - N_USERS) * 32);
                    const float2* p2 = (const float2*)((c2 < N_USERS) ? su + (size_t)c2 * 32
                                                                      : se + (size_t)(c2 - N_USERS) * 32);
                    const float2* p3 = (const float2*)((c3 < N_USERS) ? su + (size_t)c3 * 32
                                                                      : se + (size_t)(c3 - N_USERS) * 32);
                    float2 g0 = p0[sl];
                    float2 g1 = p1[sl];
                    float2 g2 = p2[sl];
                    float2 g3 = p3[sl];
                    acc.x += v0 * g0.x; acc.y += v0 * g0.y;
                    acc.x += v1 * g1.x; acc.y += v1 * g1.y;
                    acc.x += v2 * g2.x; acc.y += v2 * g2.y;
                    acc.x += v3 * g3.x; acc.y += v3 * g3.y;
                }
            }
            const float* eg = (n < N_USERS) ? su + (size_t)n * 32
                                            : se + (size_t)(n - N_USERS) * 32;
            float2 e = ((const float2*)eg)[sl];
            int kb = sl * 2;
            sA1[lr * LDA + kb + 0] = e.x + acc.x;
            sA1[lr * LDA + kb + 1] = e.y + acc.y;
            sA2[lr * LDA + kb + 0] = e.x * acc.x;
            sA2[lr * LDA + kb + 1] = e.y * acc.y;
        }
    }
    __syncthreads();

    // ---- Phase B: GEMM (R7 layout) ----
    int ty = tid >> 4, tx = tid & 15;
    constexpr int CPT = DOUT / 16;
    int colb = tx * CPT;

    float o[4][CPT];
    float ss[4] = {0.f, 0.f, 0.f, 0.f};

    if (CPT >= 2) {
        constexpr int C2 = (CPT >= 2) ? CPT / 2 : 1;
        unsigned long long accg[4][C2], accb[4][C2];
        #pragma unroll
        for (int c2 = 0; c2 < C2; c2++) {
            unsigned long long vg = pk2(bg[colb + 2 * c2], bg[colb + 2 * c2 + 1]);
            unsigned long long vb = pk2(bb[colb + 2 * c2], bb[colb + 2 * c2 + 1]);
            #pragma unroll
            for (int i = 0; i < 4; i++) { accg[i][c2] = vg; accb[i][c2] = vb; }
        }
        #pragma unroll 4
        for (int k = 0; k < DIN; k++) {
            unsigned long long pa1[4], pa2[4];
            #pragma unroll
            for (int i = 0; i < 4; i++) {
                float a1 = sA1[(ty * 4 + i) * LDA + k];
                float a2 = sA2[(ty * 4 + i) * LDA + k];
                pa1[i] = pk2(a1, a1);
                pa2[i] = pk2(a2, a2);
            }
            #pragma unroll
            for (int c2 = 0; c2 < C2; c2++) {
                unsigned long long wg = *(const unsigned long long*)(sWg + k * DOUT + colb + 2 * c2);
                unsigned long long wb = *(const unsigned long long*)(sWb + k * DOUT + colb + 2 * c2);
                #pragma unroll
                for (int i = 0; i < 4; i++) {
                    accg[i][c2] = f2fma(pa1[i], wg, accg[i][c2]);
                    accb[i][c2] = f2fma(pa2[i], wb, accb[i][c2]);
                }
            }
        }
        #pragma unroll
        for (int i = 0; i < 4; i++) {
            #pragma unroll
            for (int c2 = 0; c2 < C2; c2++) {
                float g0, g1, b0, b1;
                upk2(accg[i][c2], g0, g1);
                upk2(accb[i][c2], b0, b1);
                float x0 = leaky(g0) + leaky(b0);
                float x1 = leaky(g1) + leaky(b1);
                o[i][2 * c2]     = x0;
                o[i][2 * c2 + 1] = x1;
                ss[i] += x0 * x0 + x1 * x1;
            }
        }
    } else {
        float accg[4], accb[4];
        float big = bg[colb], bib = bb[colb];
        #pragma unroll
        for (int i = 0; i < 4; i++) { accg[i] = big; accb[i] = bib; }
        #pragma unroll 4
        for (int k = 0; k < DIN; k++) {
            float wgv = sWg[k * DOUT + colb];
            float wbv = sWb[k * DOUT + colb];
            #pragma unroll
            for (int i = 0; i < 4; i++) {
                accg[i] += sA1[(ty * 4 + i) * LDA + k] * wgv;
                accb[i] += sA2[(ty * 4 + i) * LDA + k] * wbv;
            }
        }
        #pragma unroll
        for (int i = 0; i < 4; i++) {
            float x = leaky(accg[i]) + leaky(accb[i]);
            o[i][0] = x;
            ss[i] += x * x;
        }
    }

    #pragma unroll
    for (int off = 8; off > 0; off >>= 1) {
        #pragma unroll
        for (int i = 0; i < 4; i++)
            ss[i] += __shfl_xor_sync(0xffffffffu, ss[i], off, 16);
    }

    float* oraw  = rawbuf(raw_id);
    float* onorm = normbuf(norm_id);
    #pragma unroll
    for (int i = 0; i < 4; i++) {
        float inv = 1.0f / fmaxf(sqrtf(ss[i]), 1e-12f);
        size_t rb = (size_t)(base + ty * 4 + i) * DOUT + colb;
        #pragma unroll
        for (int c = 0; c < CPT; c++) {
            if (WRITE_RAW) oraw[rb + c] = o[i][c];
            onorm[rb + c] = o[i][c] * inv;
        }
    }
}

// ---------------------------------------------------------------------------
// Final scoring: one warp per batch element.
// ---------------------------------------------------------------------------
__global__ void final_score(const int* __restrict__ users,
                            const int* __restrict__ pos,
                            const int* __restrict__ neg,
                            const float* __restrict__ ue,
                            const float* __restrict__ ee,
                            float* __restrict__ out) {
    int t    = blockIdx.x * blockDim.x + threadIdx.x;
    int w    = t >> 5;
    int lane = t & 31;
    if (w >= BB) return;

    int u  = users[w];
    int pe = pos[w];
    int ne = neg[w];
    int p  = N_USERS + pe;
    int n  = N_USERS + ne;

    float sp = 0.f, sn = 0.f;

    #pragma unroll
    for (int j = 0; j < 2; j++) {
        int k = j * 32 + lane;
        float au = ue[(size_t)u  * 64 + k];
        float ap = ee[(size_t)pe * 64 + k];
        float an = ee[(size_t)ne * 64 + k];
        sp += au * ap; sn += au * an;
    }
    #pragma unroll
    for (int j = 0; j < 2; j++) {
        int k = j * 32 + lane;
        float au = g_N1[(size_t)u * 64 + k];
        float ap = g_N1[(size_t)p * 64 + k];
        float an = g_N1[(size_t)n * 64 + k];
        sp += au * ap; sn += au * an;
    }
    {
        float au = g_N2[(size_t)u * 32 + lane];
        float ap = g_N2[(size_t)p * 32 + lane];
        float an = g_N2[(size_t)n * 32 + lane];
        sp += au * ap; sn += au * an;
    }
    if (lane < 16) {
        float au = g_N3[(size_t)u * 16 + lane];
        float ap = g_N3[(size_t)p * 16 + lane];
        float an = g_N3[(size_t)n * 16 + lane];
        sp += au * ap; sn += au * an;
    }

    #pragma unroll
    for (int off = 16; off > 0; off >>= 1) {
        sp += __shfl_xor_sync(0xffffffffu, sp, off);
        sn += __shfl_xor_sync(0xffffffffu, sn, off);
    }
    if (lane == 0) {
        out[(size_t)w * 2 + 0] = sp;
        out[(size_t)w * 2 + 1] = sn;
    }
}

// ---------------------------------------------------------------------------
// Launch
// ---------------------------------------------------------------------------
extern "C" void kernel_launch(void* const* d_in, const int* in_sizes, int n_in,
                              void* d_out, int out_size) {
    const int*   users = (const int*)  d_in[0];
    const int*   pos   = (const int*)  d_in[1];
    const int*   neg   = (const int*)  d_in[2];
    const int*   rows  = (const int*)  d_in[3];
    const int*   cols  = (const int*)  d_in[4];
    const float* vals  = (const float*)d_in[5];
    const float* ue    = (const float*)d_in[6];
    const float* ee    = (const float*)d_in[7];
    const float* Wg0 = (const float*)d_in[8],  *bg0 = (const float*)d_in[9];
    const float* Wb0 = (const float*)d_in[10], *bb0 = (const float*)d_in[11];
    const float* Wg1 = (const float*)d_in[12], *bg1 = (const float*)d_in[13];
    const float* Wb1 = (const float*)d_in[14], *bb1 = (const float*)d_in[15];
    const float* Wg2 = (const float*)d_in[16], *bg2 = (const float*)d_in[17];
    const float* Wb2 = (const float*)d_in[18], *bb2 = (const float*)d_in[19];
    float* out = (float*)d_out;

    const int smem0 = (2 * 64 * 65 + 2 * 64 * 64) * 4;  // 66048
    const int smem1 = (2 * 64 * 65 + 2 * 64 * 32) * 4;  // 49664
    const int smem2 = (2 * 64 * 33 + 2 * 32 * 16) * 4;  // 20992
    cudaFuncSetAttribute((const void*)fused_layer<64, 64, true>,
                         cudaFuncAttributeMaxDynamicSharedMemorySize, smem0);
    cudaFuncSetAttribute((const void*)fused_layer<64, 32, true>,
                         cudaFuncAttributeMaxDynamicSharedMemorySize, smem1);

    // ---- CSR build ----
    zero_cnt<<<(NN + 255) / 256, 256>>>();
    hist<<<(EE + 255) / 256, 256>>>(rows);
    scan1<<<NBLK, 256>>>();
    scan2<<<1, 256>>>();
    scan3<<<(NN + 255) / 256, 256>>>();
    permute<<<(EE + 255) / 256, 256>>>(rows, cols, vals);

    const int gemm_blocks = NN / 64;   // 3125 exact

    // ---- Layer 0: 64 -> 64 ----
    fused_layer<64, 64, true><<<gemm_blocks, 256, smem0>>>(
        0, ue, ee, Wg0, bg0, Wb0, bb0, 1, 3);

    // ---- Layer 1: 64 -> 32 ----
    fused_layer<64, 32, true><<<gemm_blocks, 256, smem1>>>(
        1, ue, ee, Wg1, bg1, Wb1, bb1, 2, 4);

    // ---- Layer 2: 32 -> 16 ----
    fused_layer<32, 16, false><<<gemm_blocks, 256, smem2>>>(
        2, ue, ee, Wg2, bg2, Wb2, bb2, 1, 5);

    // ---- Final scoring ----
    final_score<<<(BB * 32 + 255) / 256, 256>>>(users, pos, neg, ue, ee, out);
}